// round 8
// baseline (speedup 1.0000x reference)
#include <cuda_runtime.h>
#include <cuda_bf16.h>
#include <math.h>
#include <stdint.h>

// ---------------- static problem constants ----------------
#define BB   2
#define SS   4096
#define HID  2048
#define NH   32
#define HD   64
#define MTOT (BB*SS)       // 8192
#define WDIM 64
#define TILE_TOK 128
#define ATT_SCALE 0.125f
#define QSCALE (0.125f * 1.4426950408889634f)   // ATT_SCALE * log2(e)
#define GK   2048          // GEMM K
#define BKC  32            // K chunk
#define NCHUNK (GK/BKC)    // 64
#define TILE_BYTES 8192    // 128 rows * 32 bf16 * 2B
#define NSTAGE 3
#define SMEM_GEMM (NSTAGE*4*TILE_BYTES)  // 98304

typedef __nv_bfloat16 bf16;

// ---------------- scratch ----------------
__device__ float g_q[(size_t)MTOT * HID];
__device__ float g_k[(size_t)MTOT * HID];
__device__ float g_v[(size_t)MTOT * HID];
__device__ float g_o[(size_t)MTOT * HID];
__device__ bf16 g_wt[(size_t)4 * 2 * HID * HID];  // [w][hi/lo][N][K]
__device__ bf16 g_ahi[(size_t)MTOT * HID];
__device__ bf16 g_alo[(size_t)MTOT * HID];

// ---------------- baseline-PTX helpers (NO tcgen05 — harness targets sm_103) ----
__device__ __forceinline__ uint32_t smem_u32(const void* p) {
    uint32_t a;
    asm("{ .reg .u64 t; cvta.to.shared.u64 t, %1; cvt.u32.u64 %0, t; }" : "=r"(a) : "l"(p));
    return a;
}
__device__ __forceinline__ void cp_async16(uint32_t dst, const void* src) {
    asm volatile("cp.async.ca.shared.global [%0], [%1], 16;" :: "r"(dst), "l"(src));
}
#define CP_COMMIT() asm volatile("cp.async.commit_group;" ::: "memory")
#define CP_WAIT1()  asm volatile("cp.async.wait_group 1;" ::: "memory")
#define CP_WAIT0()  asm volatile("cp.async.wait_group 0;" ::: "memory")
__device__ __forceinline__ void ldm_x4(uint32_t& r0, uint32_t& r1, uint32_t& r2,
                                       uint32_t& r3, uint32_t addr) {
    asm volatile("ldmatrix.sync.aligned.m8n8.x4.shared.b16 {%0,%1,%2,%3}, [%4];"
                 : "=r"(r0), "=r"(r1), "=r"(r2), "=r"(r3) : "r"(addr));
}
__device__ __forceinline__ void mma16816(float* d,
                                         const uint32_t* a, const uint32_t* b) {
    asm volatile("mma.sync.aligned.m16n8k16.row.col.f32.bf16.bf16.f32 "
                 "{%0,%1,%2,%3}, {%4,%5,%6,%7}, {%8,%9}, {%0,%1,%2,%3};"
                 : "+f"(d[0]), "+f"(d[1]), "+f"(d[2]), "+f"(d[3])
                 : "r"(a[0]), "r"(a[1]), "r"(a[2]), "r"(a[3]), "r"(b[0]), "r"(b[1]));
}

// ---------------- pre-pass: W[K,N] f32 -> Wt hi/lo [N,K] bf16 ----------------
__global__ __launch_bounds__(256) void trans_convert(const float* __restrict__ W0,
                                                     const float* __restrict__ W1,
                                                     const float* __restrict__ W2,
                                                     const float* __restrict__ W3)
{
    __shared__ float s[64][65];
    const int z = blockIdx.z;
    const float* W = (z == 0) ? W0 : (z == 1) ? W1 : (z == 2) ? W2 : W3;
    bf16* hi = g_wt + (size_t)(2 * z) * HID * HID;
    bf16* lo = hi + (size_t)HID * HID;
    const int k0 = blockIdx.y * 64, n0 = blockIdx.x * 64;
    const int t = threadIdx.x;
    #pragma unroll
    for (int i = 0; i < 16; i++) {
        int idx = t + i * 256, kl = idx >> 6, nl = idx & 63;
        s[kl][nl] = W[(size_t)(k0 + kl) * HID + n0 + nl];
    }
    __syncthreads();
    #pragma unroll
    for (int i = 0; i < 8; i++) {
        int idx = t + i * 256, nl = idx >> 5, kl = (idx & 31) * 2;
        float f0 = s[kl][nl], f1 = s[kl + 1][nl];
        bf16 h0 = __float2bfloat16_rn(f0), h1 = __float2bfloat16_rn(f1);
        bf16 l0 = __float2bfloat16_rn(f0 - __bfloat162float(h0));
        bf16 l1 = __float2bfloat16_rn(f1 - __bfloat162float(h1));
        size_t o = (size_t)(n0 + nl) * HID + k0 + kl;
        __nv_bfloat162 ph; ph.x = h0; ph.y = h1;
        __nv_bfloat162 pl; pl.x = l0; pl.y = l1;
        *(__nv_bfloat162*)(hi + o) = ph;
        *(__nv_bfloat162*)(lo + o) = pl;
    }
}

// ---------------- pre-pass: A f32 -> hi/lo bf16 ----------------
__global__ __launch_bounds__(256) void convert_hilo(const float* __restrict__ A,
                                                    bf16* __restrict__ hi,
                                                    bf16* __restrict__ lo)
{
    size_t base = ((size_t)blockIdx.x * 256 + threadIdx.x) * 8;
    float4 a = *(const float4*)(A + base);
    float4 b = *(const float4*)(A + base + 4);
    float v[8] = {a.x, a.y, a.z, a.w, b.x, b.y, b.z, b.w};
    __align__(16) bf16 hv[8];
    __align__(16) bf16 lv[8];
    #pragma unroll
    for (int j = 0; j < 8; j++) {
        hv[j] = __float2bfloat16_rn(v[j]);
        lv[j] = __float2bfloat16_rn(v[j] - __bfloat162float(hv[j]));
    }
    *(uint4*)(hi + base) = *(uint4*)hv;
    *(uint4*)(lo + base) = *(uint4*)lv;
}

// ---------------- mma.sync 3-pass bf16 GEMM (error-compensated, 3-stage cp.async) ----
// A hi/lo [M,K] bf16 K-major; B hi/lo [N,K] bf16 K-major; C f32 [*, ldc].
// CTA 128x128, 8 warps (2 m x 4 n), warp tile 64x32, K chunk 32, 3-stage pipeline.
// smem tile layout: 16B-unit addr = row*4 + (col16 ^ ((row>>1)&3))  (conflict-free ldmatrix)
__device__ __forceinline__ void gemm_mma(const bf16* __restrict__ Ahi,
                                         const bf16* __restrict__ Alo,
                                         const bf16* __restrict__ Bhi,
                                         const bf16* __restrict__ Blo,
                                         float* __restrict__ C,
                                         int m0, int n0, int ldc)
{
    extern __shared__ char smem[];
    const uint32_t sb = smem_u32(smem);
    const int t = threadIdx.x, wid = t >> 5, lane = t & 31;
    const int warp_m = wid & 1, warp_n = wid >> 1;

    const int which = t >> 6, l64 = t & 63;   // 4 loader groups of 64 threads
    const bf16* mysrc = (which == 0) ? Ahi + (size_t)m0 * GK :
                        (which == 1) ? Alo + (size_t)m0 * GK :
                        (which == 2) ? Bhi + (size_t)n0 * GK :
                                       Blo + (size_t)n0 * GK;

    const int lrow = lane & 15;  // row within 16-row ldmatrix group
    const int lk   = lane >> 4;  // k-half selector

    float acc[4][4][4];
    #pragma unroll
    for (int mi = 0; mi < 4; mi++)
        #pragma unroll
        for (int nj = 0; nj < 4; nj++)
            #pragma unroll
            for (int r = 0; r < 4; r++) acc[mi][nj][r] = 0.f;

    // issue cp.async for chunk `c` into stage c % NSTAGE
    auto stage = [&](int c) {
        const bf16* src = mysrc + c * BKC;
        uint32_t dst = sb + (c % NSTAGE) * 4 * TILE_BYTES + which * TILE_BYTES;
        #pragma unroll
        for (int i = 0; i < 8; i++) {
            int u = l64 + 64 * i, row = u >> 2, col = u & 3;
            cp_async16(dst + (uint32_t)(row * 4 + (col ^ ((row >> 1) & 3))) * 16,
                       src + (size_t)row * GK + col * 8);
        }
        CP_COMMIT();
    };

    stage(0);
    stage(1);
    CP_WAIT1();            // chunk 0 resident (own copies)
    __syncthreads();       // all threads' chunk-0 copies visible

    for (int c = 0; c < NCHUNK; c++) {
        const uint32_t base = sb + (c % NSTAGE) * 4 * TILE_BYTES;
        #pragma unroll
        for (int ks = 0; ks < 2; ks++) {
            uint32_t ah[4][4], al[4][4], bh[4][2], bl[4][2];
            #pragma unroll
            for (int mi = 0; mi < 4; mi++) {
                int row = warp_m * 64 + mi * 16 + lrow;
                int kc  = ks * 2 + lk;
                uint32_t off = (uint32_t)(row * 4 + (kc ^ ((row >> 1) & 3))) * 16;
                ldm_x4(ah[mi][0], ah[mi][1], ah[mi][2], ah[mi][3], base + off);
                ldm_x4(al[mi][0], al[mi][1], al[mi][2], al[mi][3], base + TILE_BYTES + off);
            }
            #pragma unroll
            for (int nj2 = 0; nj2 < 2; nj2++) {
                int row = warp_n * 32 + nj2 * 16 + lrow;
                int kc  = ks * 2 + lk;
                uint32_t off = (uint32_t)(row * 4 + (kc ^ ((row >> 1) & 3))) * 16;
                uint32_t r0, r1, r2, r3;
                ldm_x4(r0, r1, r2, r3, base + 2 * TILE_BYTES + off);
                bh[nj2 * 2][0] = r0; bh[nj2 * 2][1] = r2;
                bh[nj2 * 2 + 1][0] = r1; bh[nj2 * 2 + 1][1] = r3;
                ldm_x4(r0, r1, r2, r3, base + 3 * TILE_BYTES + off);
                bl[nj2 * 2][0] = r0; bl[nj2 * 2][1] = r2;
                bl[nj2 * 2 + 1][0] = r1; bl[nj2 * 2 + 1][1] = r3;
            }
            #pragma unroll
            for (int mi = 0; mi < 4; mi++)
                #pragma unroll
                for (int nj = 0; nj < 4; nj++) {
                    mma16816(acc[mi][nj], ah[mi], bh[nj]);
                    mma16816(acc[mi][nj], ah[mi], bl[nj]);
                    mma16816(acc[mi][nj], al[mi], bh[nj]);
                }
        }
        // stage chunk c+2 into slot (c+2)%3 — untouched this iteration; the single
        // barrier publishes chunk c+1 and protects slot c%3 from stage(c+3).
        if (c + 2 < NCHUNK) {
            stage(c + 2);
            CP_WAIT1();            // chunk c+1 group complete (own copies)
        } else {
            CP_WAIT0();
        }
        __syncthreads();
    }

    // epilogue: acc registers -> C
    #pragma unroll
    for (int mi = 0; mi < 4; mi++) {
        int row = m0 + warp_m * 64 + mi * 16 + (lane >> 2);
        #pragma unroll
        for (int nj = 0; nj < 4; nj++) {
            int col = n0 + warp_n * 32 + nj * 8 + (lane & 3) * 2;
            *(float2*)(C + (size_t)row * ldc + col) =
                make_float2(acc[mi][nj][0], acc[mi][nj][1]);
            *(float2*)(C + (size_t)(row + 8) * ldc + col) =
                make_float2(acc[mi][nj][2], acc[mi][nj][3]);
        }
    }
}

__global__ __launch_bounds__(256, 1) void qkv_tc()
{
    const int which = blockIdx.x >> 4;
    const int n0 = (blockIdx.x & 15) * 128, m0 = blockIdx.y * 128;
    const bf16* bh = g_wt + (size_t)(2 * which) * HID * HID;
    float* C = (which == 0) ? g_q : (which == 1) ? g_k : g_v;
    gemm_mma(g_ahi, g_alo, bh, bh + (size_t)HID * HID, C, m0, n0, HID);
}

__global__ __launch_bounds__(256, 1) void out_tc(float* __restrict__ out)
{
    const bf16* bh = g_wt + (size_t)6 * HID * HID;
    gemm_mma(g_ahi, g_alo, bh, bh + (size_t)HID * HID, out,
             blockIdx.y * 128, blockIdx.x * 128, HID);
}

// ---------------- block-sparse sliding-tile attention (SIMT, exp2-domain) ----------------
__global__ __launch_bounds__(128) void attn_kernel(const float* __restrict__ Q,
                                                   const float* __restrict__ K,
                                                   const float* __restrict__ V,
                                                   float* __restrict__ O)
{
    extern __shared__ float4 att_smem[];
    float4* Ks = att_smem;
    float4* Vs = att_smem + TILE_TOK * 16;

    const int tt = blockIdx.x & 31;
    const int h = (blockIdx.x >> 5) & 31;
    const int b = blockIdx.x >> 10;

    const int tr = tt >> 2, tc = tt & 3;
    const int cr = min(max(tr, 1), 7);
    const int cc = min(max(tc, 1), 3);

    const int tid = threadIdx.x;
    const int th = tid >> 4, tw = tid & 15;
    const int qs = (tr * 8 + th) * WDIM + (tc * 16 + tw);

    const size_t base = ((size_t)b * SS) * HID + (size_t)h * HD;

    // q pre-scaled by ATT_SCALE*log2(e): scores land directly in log2 domain.
    float4 q[16];
    {
        const float* qp = Q + base + (size_t)qs * HID;
        #pragma unroll
        for (int d = 0; d < 16; d++) {
            float4 x = *(const float4*)(qp + d * 4);
            q[d] = make_float4(x.x * QSCALE, x.y * QSCALE, x.z * QSCALE, x.w * QSCALE);
        }
    }

    float m = -INFINITY, l = 0.f;
    float4 acc[16];
    #pragma unroll
    for (int d = 0; d < 16; d++) acc[d] = make_float4(0.f, 0.f, 0.f, 0.f);

    #pragma unroll 1
    for (int w = 0; w < 4; w++) {
        const int ktr = cr + (w >> 1) - 1;
        const int ktc = cc + (w & 1) - 1;

        __syncthreads();
        #pragma unroll
        for (int i = 0; i < 16; i++) {
            int tok = i * 8 + (tid >> 4);
            int comp = tid & 15;
            int s = (ktr * 8 + (tok >> 4)) * WDIM + (ktc * 16 + (tok & 15));
            size_t g = base + (size_t)s * HID + comp * 4;
            Ks[tok * 16 + comp] = *(const float4*)(K + g);
            Vs[tok * 16 + comp] = *(const float4*)(V + g);
        }
        __syncthreads();

        #pragma unroll 4
        for (int j = 0; j < TILE_TOK; j++) {
            float s = 0.f;
            #pragma unroll
            for (int d = 0; d < 16; d++) {
                float4 kk = Ks[j * 16 + d];
                s += q[d].x * kk.x + q[d].y * kk.y + q[d].z * kk.z + q[d].w * kk.w;
            }
            if (s > m) {                  // lazy rescale (rare after warmup)
                float f = exp2f(m - s);
                l *= f;
                #pragma unroll
                for (int d = 0; d < 16; d++) {
                    acc[d].x *= f; acc[d].y *= f; acc[d].z *= f; acc[d].w *= f;
                }
                m = s;
            }
            float p = exp2f(s - m);
            l += p;
            #pragma unroll
            for (int d = 0; d < 16; d++) {
                float4 vv = Vs[j * 16 + d];
                acc[d].x += p * vv.x; acc[d].y += p * vv.y;
                acc[d].z += p * vv.z; acc[d].w += p * vv.w;
            }
        }
    }

    const float inv_l = 1.f / l;
    __syncthreads();
    #pragma unroll
    for (int d = 0; d < 16; d++) {
        float4 a = acc[d];
        Ks[tid * 16 + d] = make_float4(a.x * inv_l, a.y * inv_l, a.z * inv_l, a.w * inv_l);
    }
    __syncthreads();
    #pragma unroll
    for (int i = 0; i < 16; i++) {
        int tok = i * 8 + (tid >> 4);
        int comp = tid & 15;
        int s = (tr * 8 + (tok >> 4)) * WDIM + (tc * 16 + (tok & 15));
        *(float4*)(O + base + (size_t)s * HID + comp * 4) = Ks[tok * 16 + comp];
    }
}

// ---------------- launch ----------------
extern "C" void kernel_launch(void* const* d_in, const int* in_sizes, int n_in,
                              void* d_out, int out_size)
{
    const float* hs = (const float*)d_in[0];
    const float* Wq = (const float*)d_in[1];
    const float* Wk = (const float*)d_in[2];
    const float* Wv = (const float*)d_in[3];
    const float* Wo = (const float*)d_in[4];
    float* out = (float*)d_out;

    float *q, *k, *v, *o;
    bf16 *ahi, *alo;
    cudaGetSymbolAddress((void**)&q, g_q);
    cudaGetSymbolAddress((void**)&k, g_k);
    cudaGetSymbolAddress((void**)&v, g_v);
    cudaGetSymbolAddress((void**)&o, g_o);
    cudaGetSymbolAddress((void**)&ahi, g_ahi);
    cudaGetSymbolAddress((void**)&alo, g_alo);

    cudaFuncSetAttribute(attn_kernel, cudaFuncAttributeMaxDynamicSharedMemorySize, 65536);
    cudaFuncSetAttribute(qkv_tc, cudaFuncAttributeMaxDynamicSharedMemorySize, SMEM_GEMM);
    cudaFuncSetAttribute(out_tc, cudaFuncAttributeMaxDynamicSharedMemorySize, SMEM_GEMM);

    // 1. weights: transpose + hi/lo split -> [N,K] bf16
    trans_convert<<<dim3(32, 32, 4), 256>>>(Wq, Wk, Wv, Wo);
    // 2. activations: hi/lo split
    convert_hilo<<<(MTOT * (size_t)HID) / 2048, 256>>>(hs, ahi, alo);
    // 3. fused QKV projection (mma.sync bf16 3-pass)
    qkv_tc<<<dim3(48, 64), 256, SMEM_GEMM>>>();
    // 4. block-sparse attention
    attn_kernel<<<BB * NH * 32, 128, 65536>>>(q, k, v, o);
    // 5. attention output: hi/lo split (reuse buffers)
    convert_hilo<<<(MTOT * (size_t)HID) / 2048, 256>>>(o, ahi, alo);
    // 6. output projection
    out_tc<<<dim3(16, 64), 256, SMEM_GEMM>>>(out);
}